// round 6
// baseline (speedup 1.0000x reference)
#include <cuda_runtime.h>

#define TPB   128
#define S_OUT 128            // one output per thread
#define M     11
#define T     4096
#define BB    32
#define AW    (S_OUT + 20 + 2)   // 150

__global__ void __launch_bounds__(TPB, 7)
gmp_kernel(const float2* __restrict__ x,
           const float*  __restrict__ W,
           float2* __restrict__ out)
{
    __shared__ float  Ak[4][AW];        // amplitude powers per k
    __shared__ float2 U  [S_OUT + 12];  // complex samples window
    __shared__ __align__(16) float wsK[4][M][12];  // W1 rows padded to 12
    __shared__ float  w0s[M];

    const int b   = blockIdx.y;
    const int t0  = blockIdx.x * S_OUT;
    const int tid = threadIdx.x;
    const float2* xb = x + (size_t)b * T;

    // ---- stage amplitude powers and samples ----
    for (int j = tid; j < S_OUT + 20; j += TPB) {
        int pos = t0 + j - 20;
        float re = 0.f, im = 0.f;
        if (pos >= 0) { float2 v = xb[pos]; re = v.x; im = v.y; }
        float a2 = re * re + im * im;
        float a  = sqrtf(a2);
        Ak[0][j] = a; Ak[1][j] = a2; Ak[2][j] = a2 * a; Ak[3][j] = a2 * a2;
        if (j >= 10) U[j - 10] = make_float2(re, im);
    }
    // ---- stage weights: W0 + padded W1 rows ----
    if (tid < M) w0s[tid] = W[tid];
    for (int j = tid; j < 484; j += TPB) {
        int k = j / 121, r = j % 121, l = r / 11, m = r % 11;
        wsK[k][l][m] = W[11 + j];
    }
    if (tid < 44) wsK[tid / 11][tid % 11][11] = 0.f;   // pad lane
    __syncthreads();

    // Output t = t0 + tid
    float c[M];
#pragma unroll
    for (int m = 0; m < M; m++) c[m] = w0s[m];

#pragma unroll
    for (int k = 0; k < 4; k++) {
        float win[21];                       // A_k(t-20+s), s=0..20
#pragma unroll
        for (int s = 0; s < 21; s++) win[s] = Ak[k][tid + s];
#pragma unroll
        for (int l = 0; l < M; l++) {
            float4 wa = *(const float4*)&wsK[k][l][0];   // broadcast LDS.128
            float4 wb = *(const float4*)&wsK[k][l][4];
            float4 wc = *(const float4*)&wsK[k][l][8];
            c[0]  = fmaf(win[l + 0],  wa.x, c[0]);
            c[1]  = fmaf(win[l + 1],  wa.y, c[1]);
            c[2]  = fmaf(win[l + 2],  wa.z, c[2]);
            c[3]  = fmaf(win[l + 3],  wa.w, c[3]);
            c[4]  = fmaf(win[l + 4],  wb.x, c[4]);
            c[5]  = fmaf(win[l + 5],  wb.y, c[5]);
            c[6]  = fmaf(win[l + 6],  wb.z, c[6]);
            c[7]  = fmaf(win[l + 7],  wb.w, c[7]);
            c[8]  = fmaf(win[l + 8],  wc.x, c[8]);
            c[9]  = fmaf(win[l + 9],  wc.y, c[9]);
            c[10] = fmaf(win[l + 10], wc.z, c[10]);
        }
    }

    // ---- epilogue: out(t) = sum_m u(t+m-10) * c_m ----
    float ar = 0.f, ai = 0.f;
#pragma unroll
    for (int m = 0; m < M; m++) {
        float2 u = U[tid + m];
        ar = fmaf(u.x, c[m], ar);
        ai = fmaf(u.y, c[m], ai);
    }

    out[(size_t)b * T + t0 + tid] = make_float2(ar, ai);
}

extern "C" void kernel_launch(void* const* d_in, const int* in_sizes, int n_in,
                              void* d_out, int out_size)
{
    const float2* x = (const float2*)d_in[0];   // (32, 4096, 2) f32
    // d_in[1] = h_0 (unused by reference)
    const float*  W = (const float*)d_in[2];    // (1, 495) f32
    float2* out = (float2*)d_out;               // (32, 4096, 2) f32

    dim3 grid(T / S_OUT, BB);                   // (32, 32) = 1024 blocks
    gmp_kernel<<<grid, TPB>>>(x, W, out);
}

// round 7
// speedup vs baseline: 1.1307x; 1.1307x over previous
#include <cuda_runtime.h>

#define TPB   128
#define OPT   64             // output-threads per block (oid)
#define S_OUT 128            // outputs per block (2 per oid)
#define M     11
#define T     4096
#define BB    32
#define AW    (S_OUT + 20 + 2)   // 150

__global__ void __launch_bounds__(TPB, 7)
gmp_kernel(const float2* __restrict__ x,
           const float*  __restrict__ W,
           float2* __restrict__ out)
{
    __shared__ float  Ak[4][AW];        // amplitude powers per k
    __shared__ float2 U  [S_OUT + 12];  // complex samples window
    __shared__ __align__(16) float wsK[4][M][12];  // W1 rows padded to 12
    __shared__ float  w0s[M];
    __shared__ float2 pc[OPT][M];       // k-partial coefficients from kh=1 group

    const int b   = blockIdx.y;
    const int t0  = blockIdx.x * S_OUT;
    const int tid = threadIdx.x;
    const int oid = tid & (OPT - 1);
    const int kh  = tid >> 6;           // 0 or 1: which k-half this thread owns
    const float2* xb = x + (size_t)b * T;

    // ---- stage amplitude powers and samples (all 128 threads) ----
    for (int j = tid; j < S_OUT + 20; j += TPB) {
        int pos = t0 + j - 20;
        float re = 0.f, im = 0.f;
        if (pos >= 0) { float2 v = xb[pos]; re = v.x; im = v.y; }
        float a2 = re * re + im * im;
        float a  = sqrtf(a2);
        Ak[0][j] = a; Ak[1][j] = a2; Ak[2][j] = a2 * a; Ak[3][j] = a2 * a2;
        if (j >= 10) U[j - 10] = make_float2(re, im);
    }
    // ---- stage weights ----
    if (tid < M) w0s[tid] = W[tid];
    for (int j = tid; j < 484; j += TPB) {
        int k = j / 121, r = j % 121, l = r / 11, m = r % 11;
        wsK[k][l][m] = W[11 + j];
    }
    if (tid < 44) wsK[tid / 11][tid % 11][11] = 0.f;   // pad lane
    __syncthreads();

    // Outputs t = t0 + 2*oid + {0,1}; this thread covers k = 2*kh, 2*kh+1
    float c0[M], c1[M];
    if (kh == 0) {
#pragma unroll
        for (int m = 0; m < M; m++) { float w = w0s[m]; c0[m] = w; c1[m] = w; }
    } else {
#pragma unroll
        for (int m = 0; m < M; m++) { c0[m] = 0.f; c1[m] = 0.f; }
    }

#pragma unroll
    for (int kk = 0; kk < 2; kk++) {
        const int k = 2 * kh + kk;
        float win[24];
#pragma unroll
        for (int s = 0; s < 24; s += 2) {
            float2 v = *(const float2*)&Ak[k][oid * 2 + s];
            win[s] = v.x; win[s + 1] = v.y;
        }
#pragma unroll
        for (int l = 0; l < M; l++) {
            float4 wa = *(const float4*)&wsK[k][l][0];   // broadcast LDS.128
            float4 wb = *(const float4*)&wsK[k][l][4];
            float4 wc = *(const float4*)&wsK[k][l][8];
            c0[0]  = fmaf(win[l + 0],  wa.x, c0[0]);  c1[0]  = fmaf(win[l + 1],  wa.x, c1[0]);
            c0[1]  = fmaf(win[l + 1],  wa.y, c0[1]);  c1[1]  = fmaf(win[l + 2],  wa.y, c1[1]);
            c0[2]  = fmaf(win[l + 2],  wa.z, c0[2]);  c1[2]  = fmaf(win[l + 3],  wa.z, c1[2]);
            c0[3]  = fmaf(win[l + 3],  wa.w, c0[3]);  c1[3]  = fmaf(win[l + 4],  wa.w, c1[3]);
            c0[4]  = fmaf(win[l + 4],  wb.x, c0[4]);  c1[4]  = fmaf(win[l + 5],  wb.x, c1[4]);
            c0[5]  = fmaf(win[l + 5],  wb.y, c0[5]);  c1[5]  = fmaf(win[l + 6],  wb.y, c1[5]);
            c0[6]  = fmaf(win[l + 6],  wb.z, c0[6]);  c1[6]  = fmaf(win[l + 7],  wb.z, c1[6]);
            c0[7]  = fmaf(win[l + 7],  wb.w, c0[7]);  c1[7]  = fmaf(win[l + 8],  wb.w, c1[7]);
            c0[8]  = fmaf(win[l + 8],  wc.x, c0[8]);  c1[8]  = fmaf(win[l + 9],  wc.x, c1[8]);
            c0[9]  = fmaf(win[l + 9],  wc.y, c0[9]);  c1[9]  = fmaf(win[l + 10], wc.y, c1[9]);
            c0[10] = fmaf(win[l + 10], wc.z, c0[10]); c1[10] = fmaf(win[l + 11], wc.z, c1[10]);
        }
    }

    // ---- exchange k-partials ----
    if (kh == 1) {
#pragma unroll
        for (int m = 0; m < M; m++) pc[oid][m] = make_float2(c0[m], c1[m]);
    }
    __syncthreads();

    if (kh == 0) {
        // combine partials and run the epilogue
        float2 ur[12];
#pragma unroll
        for (int s = 0; s < 12; s += 2) {
            float4 v = *(const float4*)&U[oid * 2 + s];
            ur[s]     = make_float2(v.x, v.y);
            ur[s + 1] = make_float2(v.z, v.w);
        }
        float ar0 = 0.f, ai0 = 0.f, ar1 = 0.f, ai1 = 0.f;
#pragma unroll
        for (int m = 0; m < M; m++) {
            float2 p = pc[oid][m];
            float t0c = c0[m] + p.x;
            float t1c = c1[m] + p.y;
            ar0 = fmaf(ur[m].x,     t0c, ar0);  ai0 = fmaf(ur[m].y,     t0c, ai0);
            ar1 = fmaf(ur[m + 1].x, t1c, ar1);  ai1 = fmaf(ur[m + 1].y, t1c, ai1);
        }
        float4* ob = (float4*)(out + (size_t)b * T + t0) + oid;
        *ob = make_float4(ar0, ai0, ar1, ai1);
    }
}

extern "C" void kernel_launch(void* const* d_in, const int* in_sizes, int n_in,
                              void* d_out, int out_size)
{
    const float2* x = (const float2*)d_in[0];   // (32, 4096, 2) f32
    // d_in[1] = h_0 (unused by reference)
    const float*  W = (const float*)d_in[2];    // (1, 495) f32
    float2* out = (float2*)d_out;               // (32, 4096, 2) f32

    dim3 grid(T / S_OUT, BB);                   // (32, 32) = 1024 blocks
    gmp_kernel<<<grid, TPB>>>(x, W, out);
}

// round 8
// speedup vs baseline: 1.1881x; 1.0507x over previous
#include <cuda_runtime.h>

#define TPB   128
#define OPT   32             // output-threads per block
#define S_OUT 64             // outputs per block (2 per output-thread)
#define M     11
#define T     4096
#define BB    32
#define AW    (S_OUT + 20 + 2)   // 86

__global__ void __launch_bounds__(TPB, 8)     // force regs<=64 -> 8 blocks/SM resident
gmp_kernel(const float2* __restrict__ x,
           const float*  __restrict__ W,
           float2* __restrict__ out)
{
    __shared__ float  Ak[4][AW];        // amplitude powers per k
    __shared__ float2 U  [S_OUT + 12];  // complex samples window
    __shared__ __align__(16) float wsK[4][M][12];  // W1 rows padded to 12
    __shared__ float  w0s[M];
    __shared__ float2 pc[3][OPT][M];    // k-partials from groups 1..3

    const int b   = blockIdx.y;
    const int t0  = blockIdx.x * S_OUT;
    const int tid = threadIdx.x;
    const int oid = tid & (OPT - 1);
    const int kg  = tid >> 5;           // 0..3 == warp id == k owned
    const float2* xb = x + (size_t)b * T;

    // ---- stage amplitude powers (84 positions) and samples (74) ----
    if (tid < S_OUT + 20) {
        int pos = t0 + tid - 20;
        float re = 0.f, im = 0.f;
        if (pos >= 0) { float2 v = xb[pos]; re = v.x; im = v.y; }
        float a2 = re * re + im * im;
        float a  = sqrtf(a2);
        Ak[0][tid] = a; Ak[1][tid] = a2; Ak[2][tid] = a2 * a; Ak[3][tid] = a2 * a2;
        if (tid >= 10) U[tid - 10] = make_float2(re, im);
    }
    // ---- stage weights ----
    if (tid < M) w0s[tid] = W[tid];
    for (int j = tid; j < 484; j += TPB) {
        int k = j / 121, r = j % 121, l = r / 11, m = r % 11;
        wsK[k][l][m] = W[11 + j];
    }
    if (tid < 44) wsK[tid / 11][tid % 11][11] = 0.f;   // pad lane
    __syncthreads();

    // Outputs t = t0 + 2*oid + {0,1}; this thread covers k = kg only
    float c0[M], c1[M];
    if (kg == 0) {
#pragma unroll
        for (int m = 0; m < M; m++) { float w = w0s[m]; c0[m] = w; c1[m] = w; }
    } else {
#pragma unroll
        for (int m = 0; m < M; m++) { c0[m] = 0.f; c1[m] = 0.f; }
    }

    {
        float win[24];                  // A_kg(t0 + 2*oid - 20 + s), s=0..23
#pragma unroll
        for (int s = 0; s < 24; s += 2) {
            float2 v = *(const float2*)&Ak[kg][oid * 2 + s];
            win[s] = v.x; win[s + 1] = v.y;
        }
#pragma unroll
        for (int l = 0; l < M; l++) {
            float4 wa = *(const float4*)&wsK[kg][l][0];   // broadcast LDS.128
            float4 wb = *(const float4*)&wsK[kg][l][4];
            float4 wc = *(const float4*)&wsK[kg][l][8];
            c0[0]  = fmaf(win[l + 0],  wa.x, c0[0]);  c1[0]  = fmaf(win[l + 1],  wa.x, c1[0]);
            c0[1]  = fmaf(win[l + 1],  wa.y, c0[1]);  c1[1]  = fmaf(win[l + 2],  wa.y, c1[1]);
            c0[2]  = fmaf(win[l + 2],  wa.z, c0[2]);  c1[2]  = fmaf(win[l + 3],  wa.z, c1[2]);
            c0[3]  = fmaf(win[l + 3],  wa.w, c0[3]);  c1[3]  = fmaf(win[l + 4],  wa.w, c1[3]);
            c0[4]  = fmaf(win[l + 4],  wb.x, c0[4]);  c1[4]  = fmaf(win[l + 5],  wb.x, c1[4]);
            c0[5]  = fmaf(win[l + 5],  wb.y, c0[5]);  c1[5]  = fmaf(win[l + 6],  wb.y, c1[5]);
            c0[6]  = fmaf(win[l + 6],  wb.z, c0[6]);  c1[6]  = fmaf(win[l + 7],  wb.z, c1[6]);
            c0[7]  = fmaf(win[l + 7],  wb.w, c0[7]);  c1[7]  = fmaf(win[l + 8],  wb.w, c1[7]);
            c0[8]  = fmaf(win[l + 8],  wc.x, c0[8]);  c1[8]  = fmaf(win[l + 9],  wc.x, c1[8]);
            c0[9]  = fmaf(win[l + 9],  wc.y, c0[9]);  c1[9]  = fmaf(win[l + 10], wc.y, c1[9]);
            c0[10] = fmaf(win[l + 10], wc.z, c0[10]); c1[10] = fmaf(win[l + 11], wc.z, c1[10]);
        }
    }

    // ---- exchange k-partials (groups 1..3 publish) ----
    if (kg != 0) {
#pragma unroll
        for (int m = 0; m < M; m++) pc[kg - 1][oid][m] = make_float2(c0[m], c1[m]);
    }
    __syncthreads();

    if (kg == 0) {   // warp 0 combines and runs the epilogue
        float2 ur[12];
#pragma unroll
        for (int s = 0; s < 12; s += 2) {
            float4 v = *(const float4*)&U[oid * 2 + s];
            ur[s]     = make_float2(v.x, v.y);
            ur[s + 1] = make_float2(v.z, v.w);
        }
        float ar0 = 0.f, ai0 = 0.f, ar1 = 0.f, ai1 = 0.f;
#pragma unroll
        for (int m = 0; m < M; m++) {
            float2 p1 = pc[0][oid][m];
            float2 p2 = pc[1][oid][m];
            float2 p3 = pc[2][oid][m];
            float t0c = c0[m] + p1.x + p2.x + p3.x;
            float t1c = c1[m] + p1.y + p2.y + p3.y;
            ar0 = fmaf(ur[m].x,     t0c, ar0);  ai0 = fmaf(ur[m].y,     t0c, ai0);
            ar1 = fmaf(ur[m + 1].x, t1c, ar1);  ai1 = fmaf(ur[m + 1].y, t1c, ai1);
        }
        float4* ob = (float4*)(out + (size_t)b * T + t0) + oid;
        *ob = make_float4(ar0, ai0, ar1, ai1);
    }
}

extern "C" void kernel_launch(void* const* d_in, const int* in_sizes, int n_in,
                              void* d_out, int out_size)
{
    const float2* x = (const float2*)d_in[0];   // (32, 4096, 2) f32
    // d_in[1] = h_0 (unused by reference)
    const float*  W = (const float*)d_in[2];    // (1, 495) f32
    float2* out = (float2*)d_out;               // (32, 4096, 2) f32

    dim3 grid(T / S_OUT, BB);                   // (64, 32) = 2048 blocks
    gmp_kernel<<<grid, TPB>>>(x, W, out);
}